// round 6
// baseline (speedup 1.0000x reference)
#include <cuda_runtime.h>
#include <math.h>

#define N_NODES 20000
#define F_IN    512
#define HDIM    64
#define L_LAYERS 8
#define E_EDGES 640000
#define C_OUT   40
#define NPAIR   2080          // 64*65/2 pairs (i<=j)
#define APR     96            // padded A row: 8 kg * 12 floats (10 used, 16B-aligned)

typedef unsigned long long ull_t;

// ---------------- device scratch (no runtime allocation allowed) ----------------
__device__ float g_h0[N_NODES * HDIM];
__device__ float g_hA[N_NODES * HDIM];
__device__ float g_hB[N_NODES * HDIM];
__device__ int   g_cnt[N_NODES];
__device__ int   g_ptr[N_NODES + 1];
__device__ int   g_cursor[N_NODES];
__device__ int2  g_edges[E_EDGES];            // x = col index, y = float bits of weight
__device__ int   g_pi[NPAIR];
__device__ int   g_pj[NPAIR];
__device__ float g_Apack[NPAIR * APR];        // [p][kg][12]: 5 duplicated k-pairs + pad

#define FMA_F32X2(d, a, b, c) \
    asm("fma.rn.f32x2 %0, %1, %2, %3;" : "=l"(d) : "l"(a), "l"(b), "l"(c))

__device__ __forceinline__ ull_t pack2(float lo, float hi) {
    ull_t r;
    asm("mov.b64 %0, {%1, %2};" : "=l"(r) : "f"(lo), "f"(hi));
    return r;
}

// ---------------- init: zero counters + pair index tables ----------------
__global__ void init_kernel() {
    int t = blockIdx.x * blockDim.x + threadIdx.x;
    if (t < N_NODES) g_cnt[t] = 0;
    if (t < NPAIR) {
        int i = 0, off = 0;
        while (off + (HDIM - i) <= t) { off += HDIM - i; i++; }
        g_pi[t] = i;
        g_pj[t] = i + (t - off);
    }
}

__global__ void hist_kernel(const int* __restrict__ row) {
    int e = blockIdx.x * blockDim.x + threadIdx.x;
    if (e < E_EDGES) atomicAdd(&g_cnt[row[e]], 1);
}

// single-block exclusive scan over 20000 counters -> g_ptr, g_cursor
__global__ void scan_kernel() {
    const int T = 1024;
    const int PER = (N_NODES + T - 1) / T;  // 20
    __shared__ int sums[T];
    int t = threadIdx.x;
    int base = t * PER;
    int local[PER];
    int s = 0;
#pragma unroll
    for (int i = 0; i < PER; i++) {
        int idx = base + i;
        int v = (idx < N_NODES) ? g_cnt[idx] : 0;
        local[i] = s;
        s += v;
    }
    sums[t] = s;
    __syncthreads();
    for (int off = 1; off < T; off <<= 1) {
        int v = (t >= off) ? sums[t - off] : 0;
        __syncthreads();
        sums[t] += v;
        __syncthreads();
    }
    int offset = (t == 0) ? 0 : sums[t - 1];
#pragma unroll
    for (int i = 0; i < PER; i++) {
        int idx = base + i;
        if (idx < N_NODES) {
            int p = offset + local[i];
            g_ptr[idx] = p;
            g_cursor[idx] = p;
        }
    }
    if (t == T - 1) g_ptr[N_NODES] = sums[T - 1];
}

__global__ void scatter_kernel(const int* __restrict__ row, const int* __restrict__ col,
                               const float* __restrict__ ew) {
    int e = blockIdx.x * blockDim.x + threadIdx.x;
    if (e < E_EDGES) {
        int r = row[e];
        int pos = atomicAdd(&g_cursor[r], 1);
        g_edges[pos] = make_int2(col[e], __float_as_int(ew[e]));
    }
}

// A[p][k] = W[(i,j),k] + (i!=j ? W[(j,i),k] : 0), duplicated pairs, padded layout
__global__ void apack_kernel(const float* __restrict__ lin1_w) {
    int idx = blockIdx.x * blockDim.x + threadIdx.x;   // 0 .. NPAIR*C_OUT-1
    if (idx < NPAIR * C_OUT) {
        int p = idx / C_OUT;
        int k = idx % C_OUT;
        int i = g_pi[p], j = g_pj[p];
        float v = lin1_w[(i * HDIM + j) * C_OUT + k];
        if (i != j) v += lin1_w[(j * HDIM + i) * C_OUT + k];
        int kg = k / 5, kc = k % 5;
        float* dst = &g_Apack[p * APR + kg * 12 + kc * 2];
        dst[0] = v;
        dst[1] = v;
    }
}

// ---------------- lin0 GEMM: h0 = relu(x @ W + b) ; also seed h ----------------
// RT=144 rows/block -> grid 139 (one full wave on 148 SMs). 256 threads.
// Thread tile: 9 rows (ty=tid>>4) x 4 cols (tx=tid&15), f32x2 accumulators.
#define L0_RT 144
#define L0_XS 149   // padded row stride for Xs (conflict-free STS)
__global__ void lin0_kernel(const float* __restrict__ x, const float* __restrict__ w,
                            const float* __restrict__ b) {
    __shared__ float Xs[32][L0_XS];   // transposed x tile: Xs[k][row]
    __shared__ float Ws[32][64];
    int tid = threadIdx.x;
    int tx = tid & 15;
    int ty = tid >> 4;
    int row0 = blockIdx.x * L0_RT;

    ull_t acc0[9], acc1[9];
#pragma unroll
    for (int m = 0; m < 9; m++) { acc0[m] = 0ull; acc1[m] = 0ull; }

    for (int k0 = 0; k0 < F_IN; k0 += 32) {
        // load X tile (144 rows x 32 k) transposed: 1152 float4 slots
#pragma unroll
        for (int q = 0; q < 5; q++) {
            int idx = tid + 256 * q;
            if (idx < L0_RT * 8) {
                int r = idx >> 3;
                int k4 = idx & 7;
                int gr = row0 + r;
                float4 v = make_float4(0.f, 0.f, 0.f, 0.f);
                if (gr < N_NODES) v = *(const float4*)&x[gr * F_IN + k0 + k4 * 4];
                Xs[k4 * 4 + 0][r] = v.x;
                Xs[k4 * 4 + 1][r] = v.y;
                Xs[k4 * 4 + 2][r] = v.z;
                Xs[k4 * 4 + 3][r] = v.w;
            }
        }
        // load W tile (32 x 64)
#pragma unroll
        for (int q = 0; q < 2; q++) {
            int idx = tid + 256 * q;
            int kk = idx >> 4;
            int c4 = idx & 15;
            *(float4*)&Ws[kk][c4 * 4] = *(const float4*)&w[(k0 + kk) * HDIM + c4 * 4];
        }
        __syncthreads();
#pragma unroll
        for (int kk = 0; kk < 32; kk++) {
            double2 bd = *(const double2*)&Ws[kk][tx * 4];
            ull_t b01 = __double_as_longlong(bd.x);
            ull_t b23 = __double_as_longlong(bd.y);
#pragma unroll
            for (int m = 0; m < 9; m++) {
                float a = Xs[kk][ty * 9 + m];
                ull_t pa = pack2(a, a);
                FMA_F32X2(acc0[m], pa, b01, acc0[m]);
                FMA_F32X2(acc1[m], pa, b23, acc1[m]);
            }
        }
        __syncthreads();
    }

    float4 bv = *(const float4*)&b[tx * 4];
#pragma unroll
    for (int m = 0; m < 9; m++) {
        int gr = row0 + ty * 9 + m;
        if (gr < N_NODES) {
            float4 r;
            r.x = fmaxf(__uint_as_float((unsigned)(acc0[m] & 0xffffffffull)) + bv.x, 0.f);
            r.y = fmaxf(__uint_as_float((unsigned)(acc0[m] >> 32)) + bv.y, 0.f);
            r.z = fmaxf(__uint_as_float((unsigned)(acc1[m] & 0xffffffffull)) + bv.z, 0.f);
            r.w = fmaxf(__uint_as_float((unsigned)(acc1[m] >> 32)) + bv.w, 0.f);
            *(float4*)&g_h0[gr * HDIM + tx * 4] = r;
            *(float4*)&g_hA[gr * HDIM + tx * 4] = r;
        }
    }
}

// ---------------- fused GCN2 layer (round-2/4 proven scalar-gather version) ----------------
// one warp per node; lane owns columns lane and lane+32
__global__ void layer_kernel(const float* __restrict__ hin, float* __restrict__ hout,
                             const float* __restrict__ convw, float one_minus_beta, float beta) {
    __shared__ float Wc[64][64];
    int tid = threadIdx.x;
#pragma unroll
    for (int q = 0; q < 4; q++) {
        int idx = tid + 256 * q;
        *(float4*)&Wc[0][idx * 4] = *(const float4*)&convw[idx * 4];
    }
    __syncthreads();

    int warp = tid >> 5, lane = tid & 31;
    int node = blockIdx.x * 8 + warp;
    if (node >= N_NODES) return;

    int s = g_ptr[node];
    int e = g_ptr[node + 1];
    float acc0 = 0.f, acc1 = 0.f;
    int i = s;
    if ((i & 1) && i < e) {
        int2 a0 = g_edges[i];
        float wv = __int_as_float(a0.y);
        acc0 = fmaf(wv, __ldg(&hin[a0.x * HDIM + lane]), acc0);
        acc1 = fmaf(wv, __ldg(&hin[a0.x * HDIM + 32 + lane]), acc1);
        i++;
    }
    for (; i + 4 <= e; i += 4) {
        int4 e01 = *(const int4*)&g_edges[i];
        int4 e23 = *(const int4*)&g_edges[i + 2];
        float v00 = __ldg(&hin[e01.x * HDIM + lane]);
        float v01 = __ldg(&hin[e01.x * HDIM + 32 + lane]);
        float v10 = __ldg(&hin[e01.z * HDIM + lane]);
        float v11 = __ldg(&hin[e01.z * HDIM + 32 + lane]);
        float v20 = __ldg(&hin[e23.x * HDIM + lane]);
        float v21 = __ldg(&hin[e23.x * HDIM + 32 + lane]);
        float v30 = __ldg(&hin[e23.z * HDIM + lane]);
        float v31 = __ldg(&hin[e23.z * HDIM + 32 + lane]);
        acc0 = fmaf(__int_as_float(e01.y), v00, acc0);
        acc1 = fmaf(__int_as_float(e01.y), v01, acc1);
        acc0 = fmaf(__int_as_float(e01.w), v10, acc0);
        acc1 = fmaf(__int_as_float(e01.w), v11, acc1);
        acc0 = fmaf(__int_as_float(e23.y), v20, acc0);
        acc1 = fmaf(__int_as_float(e23.y), v21, acc1);
        acc0 = fmaf(__int_as_float(e23.w), v30, acc0);
        acc1 = fmaf(__int_as_float(e23.w), v31, acc1);
    }
    for (; i < e; i++) {
        int2 a0 = g_edges[i];
        float wv = __int_as_float(a0.y);
        acc0 = fmaf(wv, __ldg(&hin[a0.x * HDIM + lane]), acc0);
        acc1 = fmaf(wv, __ldg(&hin[a0.x * HDIM + 32 + lane]), acc1);
    }

    float o0 = 0.9f * acc0 + 0.1f * g_h0[node * HDIM + lane];
    float o1 = 0.9f * acc1 + 0.1f * g_h0[node * HDIM + 32 + lane];

    float gg0 = 0.f, gg1 = 0.f;
#pragma unroll
    for (int k = 0; k < 32; k++) {
        float ok = __shfl_sync(0xffffffffu, o0, k);
        gg0 = fmaf(ok, Wc[k][lane], gg0);
        gg1 = fmaf(ok, Wc[k][lane + 32], gg1);
    }
#pragma unroll
    for (int k = 0; k < 32; k++) {
        float ok = __shfl_sync(0xffffffffu, o1, k);
        gg0 = fmaf(ok, Wc[32 + k][lane], gg0);
        gg1 = fmaf(ok, Wc[32 + k][lane + 32], gg1);
    }
    float r0 = fmaxf(one_minus_beta * o0 + beta * gg0, 0.f);
    float r1 = fmaxf(one_minus_beta * o1 + beta * gg1, 0.f);
    hout[node * HDIM + lane] = r0;
    hout[node * HDIM + 32 + lane] = r1;
}

// ---------------- final: z[n,k] = sum_p P[p,n]*A[p,k] (symmetric-pair GEMM) ----------------
// FM=64 nodes, 128 threads (4 warps). Thread tile: 4 nodes x 5 k.
#define FM 64
#define FTHR 128
#define KC 32
#define OFF_P   0                          // [KC][64]   (2048)
#define OFF_A   (OFF_P + KC * FM)          // [KC][APR]  (3072)
#define OFF_H   (OFF_A + KC * APR)         // [64][65]   (4160)
#define OFF_N2  (OFF_H + FM * 65)          // [64]
#define FK_SMEM_FLOATS (OFF_N2 + FM)
#define FK_SMEM_BYTES  (FK_SMEM_FLOATS * 4)
// zs overlaid on Pt/At after the main loop (needs 64*40=2560 <= 5120)

__global__ void final_kernel(const float* __restrict__ hin, const float* __restrict__ b1,
                             float* __restrict__ out) {
    extern __shared__ float smem[];
    float* Pt  = smem + OFF_P;
    float* At  = smem + OFF_A;
    float* hs  = smem + OFF_H;
    float* n2s = smem + OFF_N2;
    float* zs  = smem + OFF_P;             // overlay, used after main loop

    int tid = threadIdx.x;
    int n0 = blockIdx.x * FM;

    // load h tile [64][64] -> hs stride 65
#pragma unroll
    for (int q = 0; q < 8; q++) {
        int idx = tid + FTHR * q;          // 0..1023 float4 slots
        int nd = idx >> 4;
        int j4 = idx & 15;
        int gn = n0 + nd;
        float4 v = make_float4(0.f, 0.f, 0.f, 0.f);
        if (gn < N_NODES) v = *(const float4*)&hin[gn * HDIM + j4 * 4];
        float* hr = hs + nd * 65 + j4 * 4;
        hr[0] = v.x; hr[1] = v.y; hr[2] = v.z; hr[3] = v.w;
    }
    __syncthreads();

    if (tid < FM) {
        float s = 0.f;
        const float* hr = hs + tid * 65;
#pragma unroll
        for (int j = 0; j < 64; j++) s = fmaf(hr[j], hr[j], s);
        n2s[tid] = s;
    }

    int g = tid >> 3;         // node group 0..15: nodes 4g..4g+3
    int kg = tid & 7;         // k group 0..7: ks kg*5..kg*5+4
    int kbase = kg * 5;

    ull_t acc0[5], acc1[5];
#pragma unroll
    for (int c = 0; c < 5; c++) { acc0[c] = 0ull; acc1[c] = 0ull; }

    for (int pc = 0; pc < NPAIR; pc += KC) {
        __syncthreads();
        // stage A chunk: KC*APR floats = 768 float4, contiguous
        {
            const float4* src = (const float4*)&g_Apack[pc * APR];
#pragma unroll
            for (int q = 0; q < KC * APR / 4 / FTHR; q++) {   // 6
                int v = tid + FTHR * q;
                *(float4*)&At[v * 4] = src[v];
            }
        }
        // build P chunk: P[pl][nd] = h[nd][i]*h[nd][j]
#pragma unroll
        for (int q = 0; q < KC * FM / FTHR; q++) {            // 16
            int t = tid + FTHR * q;
            int pl = t >> 6;
            int nd = t & 63;
            int p = pc + pl;
            int i = __ldg(&g_pi[p]);
            int j = __ldg(&g_pj[p]);
            Pt[pl * FM + nd] = hs[nd * 65 + i] * hs[nd * 65 + j];
        }
        __syncthreads();

#pragma unroll 4
        for (int kk = 0; kk < KC; kk++) {
            double2 pd = *(const double2*)&Pt[kk * FM + g * 4];
            ull_t p01 = __double_as_longlong(pd.x);
            ull_t p23 = __double_as_longlong(pd.y);
            const float* arow = At + kk * APR + kg * 12;
            double2 a01 = *(const double2*)arow;
            double2 a23 = *(const double2*)(arow + 4);
            ull_t a4 = *(const ull_t*)(arow + 8);
            ull_t a0 = __double_as_longlong(a01.x);
            ull_t a1 = __double_as_longlong(a01.y);
            ull_t a2 = __double_as_longlong(a23.x);
            ull_t a3 = __double_as_longlong(a23.y);
            FMA_F32X2(acc0[0], p01, a0, acc0[0]);
            FMA_F32X2(acc1[0], p23, a0, acc1[0]);
            FMA_F32X2(acc0[1], p01, a1, acc0[1]);
            FMA_F32X2(acc1[1], p23, a1, acc1[1]);
            FMA_F32X2(acc0[2], p01, a2, acc0[2]);
            FMA_F32X2(acc1[2], p23, a2, acc1[2]);
            FMA_F32X2(acc0[3], p01, a3, acc0[3]);
            FMA_F32X2(acc1[3], p23, a3, acc1[3]);
            FMA_F32X2(acc0[4], p01, a4, acc0[4]);
            FMA_F32X2(acc1[4], p23, a4, acc1[4]);
        }
    }
    __syncthreads();   // done with Pt/At; zs overlay becomes safe

    // unpack accumulators -> zs[node][k]
#pragma unroll
    for (int c = 0; c < 5; c++) {
        int k = kbase + c;
        zs[(g * 4 + 0) * C_OUT + k] = __uint_as_float((unsigned)(acc0[c] & 0xffffffffull));
        zs[(g * 4 + 1) * C_OUT + k] = __uint_as_float((unsigned)(acc0[c] >> 32));
        zs[(g * 4 + 2) * C_OUT + k] = __uint_as_float((unsigned)(acc1[c] & 0xffffffffull));
        zs[(g * 4 + 3) * C_OUT + k] = __uint_as_float((unsigned)(acc1[c] >> 32));
    }
    __syncthreads();

    // per-node hyperbolic epilogue + log_softmax
    if (tid < FM) {
        int gn = n0 + tid;
        if (gn < N_NODES) {
            const float MAXN = 1.0f - 4e-3f;
            float n2 = fmaxf(n2s[tid], 1e-15f);   // ||o|| = ||h||^2
            float pn = fminf(n2, MAXN);
            float t = atanhf(pn);
            float scale = t / n2;

            float u[C_OUT];
            float un2 = 0.f;
#pragma unroll
            for (int k = 0; k < C_OUT; k++) {
                float v = scale * zs[tid * C_OUT + k] + b1[k];
                u[k] = v;
                un2 = fmaf(v, v, un2);
            }
            float un = fmaxf(sqrtf(un2), 1e-15f);
            float th = tanhf(un);
            float gsc = fminf(th, MAXN) / un;

            float m = -INFINITY;
#pragma unroll
            for (int k = 0; k < C_OUT; k++) {
                u[k] *= gsc;
                m = fmaxf(m, u[k]);
            }
            float se = 0.f;
#pragma unroll
            for (int k = 0; k < C_OUT; k++) se += expf(u[k] - m);
            float lse = m + logf(se);
#pragma unroll
            for (int k = 0; k < C_OUT; k++) out[gn * C_OUT + k] = u[k] - lse;
        }
    }
}

// ---------------- launch ----------------
// Order note: lin0 is hoisted to the 4th launch slot (legal: it only reads x/w/b)
// so the fixed ncu capture window (-s 5 -c 1), which previously always landed on
// scatter_kernel, lands on lin0 and gives us per-kernel evidence next round.
extern "C" void kernel_launch(void* const* d_in, const int* in_sizes, int n_in,
                              void* d_out, int out_size) {
    const float* x      = (const float*)d_in[0];
    const int*   row    = (const int*)d_in[1];
    const int*   col    = (const int*)d_in[2];
    const float* ew     = (const float*)d_in[3];
    const float* lin0_w = (const float*)d_in[4];
    const float* lin0_b = (const float*)d_in[5];
    const float* conv_w = (const float*)d_in[6];
    const float* lin1_w = (const float*)d_in[7];
    const float* lin1_b = (const float*)d_in[8];
    float* out = (float*)d_out;

    float* hA = nullptr;
    float* hB = nullptr;
    cudaGetSymbolAddress((void**)&hA, g_hA);
    cudaGetSymbolAddress((void**)&hB, g_hB);

    init_kernel<<<(N_NODES + 255) / 256, 256>>>();                       // 1
    hist_kernel<<<(E_EDGES + 255) / 256, 256>>>(row);                    // 2
    scan_kernel<<<1, 1024>>>();                                          // 3
    lin0_kernel<<<(N_NODES + L0_RT - 1) / L0_RT, 256>>>(x, lin0_w, lin0_b); // 4 <- profiled slot
    scatter_kernel<<<(E_EDGES + 255) / 256, 256>>>(row, col, ew);        // 5
    apack_kernel<<<(NPAIR * C_OUT + 255) / 256, 256>>>(lin1_w);          // 6

    const float* hin = hA;
    float* hout = hB;
    for (int l = 0; l < L_LAYERS; l++) {
        float beta = logf(0.5f / (float)(l + 1) + 1.0f);
        layer_kernel<<<(N_NODES + 7) / 8, 256>>>(hin, hout, conv_w + l * HDIM * HDIM,
                                                 1.0f - beta, beta);
        const float* tmp = hin;
        hin = hout;
        hout = (float*)tmp;
    }

    cudaFuncSetAttribute(final_kernel, cudaFuncAttributeMaxDynamicSharedMemorySize,
                         FK_SMEM_BYTES);
    final_kernel<<<(N_NODES + FM - 1) / FM, FTHR, FK_SMEM_BYTES>>>(hin, lin1_b, out);
}

// round 7
// speedup vs baseline: 1.1047x; 1.1047x over previous
#include <cuda_runtime.h>
#include <math.h>

#define N_NODES 20000
#define F_IN    512
#define HDIM    64
#define L_LAYERS 8
#define E_EDGES 640000
#define C_OUT   40
#define NPAIR   2080          // 64*65/2 pairs (i<=j)
#define APR     96            // padded A row: 8 kg * 12 floats (10 used, 16B-aligned)

typedef unsigned long long ull_t;

// ---------------- device scratch (no runtime allocation allowed) ----------------
__device__ float g_h0[N_NODES * HDIM];
__device__ float g_hA[N_NODES * HDIM];
__device__ float g_hB[N_NODES * HDIM];
__device__ int   g_cnt[N_NODES];
__device__ int   g_ptr[N_NODES + 1];
__device__ int   g_cursor[N_NODES];
__device__ int2  g_edges[E_EDGES];            // x = col index, y = float bits of weight
__device__ int   g_pi[NPAIR];
__device__ int   g_pj[NPAIR];
__device__ float g_Apack[NPAIR * APR];        // [p][kg][12]: 5 duplicated k-pairs + pad

#define FMA_F32X2(d, a, b, c) \
    asm("fma.rn.f32x2 %0, %1, %2, %3;" : "=l"(d) : "l"(a), "l"(b), "l"(c))

__device__ __forceinline__ ull_t pack2(float lo, float hi) {
    ull_t r;
    asm("mov.b64 %0, {%1, %2};" : "=l"(r) : "f"(lo), "f"(hi));
    return r;
}

// ---------------- init: zero counters + pair index tables ----------------
__global__ void init_kernel() {
    int t = blockIdx.x * blockDim.x + threadIdx.x;
    if (t < N_NODES) g_cnt[t] = 0;
    if (t < NPAIR) {
        int i = 0, off = 0;
        while (off + (HDIM - i) <= t) { off += HDIM - i; i++; }
        g_pi[t] = i;
        g_pj[t] = i + (t - off);
    }
}

__global__ void hist_kernel(const int* __restrict__ row) {
    int e = blockIdx.x * blockDim.x + threadIdx.x;
    if (e < E_EDGES) atomicAdd(&g_cnt[row[e]], 1);
}

// single-block exclusive scan over 20000 counters -> g_ptr, g_cursor
__global__ void scan_kernel() {
    const int T = 1024;
    const int PER = (N_NODES + T - 1) / T;  // 20
    __shared__ int sums[T];
    int t = threadIdx.x;
    int base = t * PER;
    int local[PER];
    int s = 0;
#pragma unroll
    for (int i = 0; i < PER; i++) {
        int idx = base + i;
        int v = (idx < N_NODES) ? g_cnt[idx] : 0;
        local[i] = s;
        s += v;
    }
    sums[t] = s;
    __syncthreads();
    for (int off = 1; off < T; off <<= 1) {
        int v = (t >= off) ? sums[t - off] : 0;
        __syncthreads();
        sums[t] += v;
        __syncthreads();
    }
    int offset = (t == 0) ? 0 : sums[t - 1];
#pragma unroll
    for (int i = 0; i < PER; i++) {
        int idx = base + i;
        if (idx < N_NODES) {
            int p = offset + local[i];
            g_ptr[idx] = p;
            g_cursor[idx] = p;
        }
    }
    if (t == T - 1) g_ptr[N_NODES] = sums[T - 1];
}

__global__ void scatter_kernel(const int* __restrict__ row, const int* __restrict__ col,
                               const float* __restrict__ ew) {
    int e = blockIdx.x * blockDim.x + threadIdx.x;
    if (e < E_EDGES) {
        int r = row[e];
        int pos = atomicAdd(&g_cursor[r], 1);
        g_edges[pos] = make_int2(col[e], __float_as_int(ew[e]));
    }
}

// A[p][k] = W[(i,j),k] + (i!=j ? W[(j,i),k] : 0), duplicated pairs, padded layout
__global__ void apack_kernel(const float* __restrict__ lin1_w) {
    int idx = blockIdx.x * blockDim.x + threadIdx.x;   // 0 .. NPAIR*C_OUT-1
    if (idx < NPAIR * C_OUT) {
        int p = idx / C_OUT;
        int k = idx % C_OUT;
        int i = g_pi[p], j = g_pj[p];
        float v = lin1_w[(i * HDIM + j) * C_OUT + k];
        if (i != j) v += lin1_w[(j * HDIM + i) * C_OUT + k];
        int kg = k / 5, kc = k % 5;
        float* dst = &g_Apack[p * APR + kg * 12 + kc * 2];
        dst[0] = v;
        dst[1] = v;
    }
}

// ---------------- lin0 GEMM: h0 = relu(x @ W + b) ; also seed h ----------------
// RT=144 rows/block -> grid 139 (one wave). 256 threads.
// Register-prefetch double buffering: load chunk c+1 while computing chunk c.
#define L0_RT 144
#define L0_XS 149   // padded row stride for Xs (conflict-free STS)
#define L0_NCHUNK (F_IN / 32)   // 16
__global__ void lin0_kernel(const float* __restrict__ x, const float* __restrict__ w,
                            const float* __restrict__ b) {
    __shared__ float Xs[32][L0_XS];   // transposed x tile: Xs[k][row]
    __shared__ float Ws[32][64];
    int tid = threadIdx.x;
    int tx = tid & 15;
    int ty = tid >> 4;
    int row0 = blockIdx.x * L0_RT;

    ull_t acc0[9], acc1[9];
#pragma unroll
    for (int m = 0; m < 9; m++) { acc0[m] = 0ull; acc1[m] = 0ull; }

    // prefetch registers
    float4 xv[5];
    float4 wv[2];

    // precomputed per-thread load/store coordinates
    int xr[5], xk4[5];
    bool xok[5];
#pragma unroll
    for (int q = 0; q < 5; q++) {
        int idx = tid + 256 * q;
        xok[q] = (idx < L0_RT * 8);
        xr[q] = idx >> 3;
        xk4[q] = idx & 7;
    }
    int wkk[2], wc4[2];
#pragma unroll
    for (int q = 0; q < 2; q++) {
        int idx = tid + 256 * q;
        wkk[q] = idx >> 4;
        wc4[q] = idx & 15;
    }

    // load chunk 0 into registers
#pragma unroll
    for (int q = 0; q < 5; q++) {
        xv[q] = make_float4(0.f, 0.f, 0.f, 0.f);
        if (xok[q]) {
            int gr = row0 + xr[q];
            if (gr < N_NODES) xv[q] = *(const float4*)&x[gr * F_IN + xk4[q] * 4];
        }
    }
#pragma unroll
    for (int q = 0; q < 2; q++)
        wv[q] = *(const float4*)&w[wkk[q] * HDIM + wc4[q] * 4];

    for (int c = 0; c < L0_NCHUNK; c++) {
        __syncthreads();   // previous compute done reading smem
        // store prefetched regs -> smem
#pragma unroll
        for (int q = 0; q < 5; q++) {
            if (xok[q]) {
                int r = xr[q], k4 = xk4[q];
                Xs[k4 * 4 + 0][r] = xv[q].x;
                Xs[k4 * 4 + 1][r] = xv[q].y;
                Xs[k4 * 4 + 2][r] = xv[q].z;
                Xs[k4 * 4 + 3][r] = xv[q].w;
            }
        }
#pragma unroll
        for (int q = 0; q < 2; q++)
            *(float4*)&Ws[wkk[q]][wc4[q] * 4] = wv[q];
        __syncthreads();

        // issue prefetch for chunk c+1 (latency hidden under compute below)
        if (c + 1 < L0_NCHUNK) {
            int k0 = (c + 1) * 32;
#pragma unroll
            for (int q = 0; q < 5; q++) {
                if (xok[q]) {
                    int gr = row0 + xr[q];
                    if (gr < N_NODES)
                        xv[q] = *(const float4*)&x[gr * F_IN + k0 + xk4[q] * 4];
                }
            }
#pragma unroll
            for (int q = 0; q < 2; q++)
                wv[q] = *(const float4*)&w[(k0 + wkk[q]) * HDIM + wc4[q] * 4];
        }

        // compute chunk c
#pragma unroll
        for (int kk = 0; kk < 32; kk++) {
            double2 bd = *(const double2*)&Ws[kk][tx * 4];
            ull_t b01 = __double_as_longlong(bd.x);
            ull_t b23 = __double_as_longlong(bd.y);
#pragma unroll
            for (int m = 0; m < 9; m++) {
                float a = Xs[kk][ty * 9 + m];
                ull_t pa = pack2(a, a);
                FMA_F32X2(acc0[m], pa, b01, acc0[m]);
                FMA_F32X2(acc1[m], pa, b23, acc1[m]);
            }
        }
    }

    float4 bv = *(const float4*)&b[tx * 4];
#pragma unroll
    for (int m = 0; m < 9; m++) {
        int gr = row0 + ty * 9 + m;
        if (gr < N_NODES) {
            float4 r;
            r.x = fmaxf(__uint_as_float((unsigned)(acc0[m] & 0xffffffffull)) + bv.x, 0.f);
            r.y = fmaxf(__uint_as_float((unsigned)(acc0[m] >> 32)) + bv.y, 0.f);
            r.z = fmaxf(__uint_as_float((unsigned)(acc1[m] & 0xffffffffull)) + bv.z, 0.f);
            r.w = fmaxf(__uint_as_float((unsigned)(acc1[m] >> 32)) + bv.w, 0.f);
            *(float4*)&g_h0[gr * HDIM + tx * 4] = r;
            *(float4*)&g_hA[gr * HDIM + tx * 4] = r;
        }
    }
}

// ---------------- fused GCN2 layer (R5 float2-gather version — measured faster) ----------------
// one warp per node; lane owns columns 2*lane, 2*lane+1 via float2 loads,
// scalar FMA chains (two independent accumulators, no packing ALU).
__global__ void layer_kernel(const float* __restrict__ hin, float* __restrict__ hout,
                             const float* __restrict__ convw, float one_minus_beta, float beta) {
    __shared__ float Wc[64][64];
    int tid = threadIdx.x;
#pragma unroll
    for (int q = 0; q < 4; q++) {
        int idx = tid + 256 * q;
        *(float4*)&Wc[0][idx * 4] = *(const float4*)&convw[idx * 4];
    }
    __syncthreads();

    int warp = tid >> 5, lane = tid & 31;
    int node = blockIdx.x * 8 + warp;
    if (node >= N_NODES) return;

    int s = g_ptr[node];
    int e = g_ptr[node + 1];
    float acc0 = 0.f, acc1 = 0.f;
    int i = s;
    if ((i & 1) && i < e) {
        int2 a0 = g_edges[i];
        float wv = __int_as_float(a0.y);
        float2 v = __ldg((const float2*)&hin[a0.x * HDIM + 2 * lane]);
        acc0 = fmaf(wv, v.x, acc0);
        acc1 = fmaf(wv, v.y, acc1);
        i++;
    }
    for (; i + 4 <= e; i += 4) {
        int4 e01 = *(const int4*)&g_edges[i];
        int4 e23 = *(const int4*)&g_edges[i + 2];
        float2 v0 = __ldg((const float2*)&hin[e01.x * HDIM + 2 * lane]);
        float2 v1 = __ldg((const float2*)&hin[e01.z * HDIM + 2 * lane]);
        float2 v2 = __ldg((const float2*)&hin[e23.x * HDIM + 2 * lane]);
        float2 v3 = __ldg((const float2*)&hin[e23.z * HDIM + 2 * lane]);
        float w0 = __int_as_float(e01.y);
        float w1 = __int_as_float(e01.w);
        float w2 = __int_as_float(e23.y);
        float w3 = __int_as_float(e23.w);
        acc0 = fmaf(w0, v0.x, acc0);
        acc1 = fmaf(w0, v0.y, acc1);
        acc0 = fmaf(w1, v1.x, acc0);
        acc1 = fmaf(w1, v1.y, acc1);
        acc0 = fmaf(w2, v2.x, acc0);
        acc1 = fmaf(w2, v2.y, acc1);
        acc0 = fmaf(w3, v3.x, acc0);
        acc1 = fmaf(w3, v3.y, acc1);
    }
    for (; i < e; i++) {
        int2 a0 = g_edges[i];
        float wv = __int_as_float(a0.y);
        float2 v = __ldg((const float2*)&hin[a0.x * HDIM + 2 * lane]);
        acc0 = fmaf(wv, v.x, acc0);
        acc1 = fmaf(wv, v.y, acc1);
    }

    float2 h0v = *(const float2*)&g_h0[node * HDIM + 2 * lane];
    float o0 = 0.9f * acc0 + 0.1f * h0v.x;   // col 2*lane
    float o1 = 0.9f * acc1 + 0.1f * h0v.y;   // col 2*lane+1

    // conv: gg[c] = sum_k o[k] * Wc[k][c]; k=2m from o0 shuffles, k=2m+1 from o1
    float gg0 = 0.f, gg1 = 0.f;
#pragma unroll
    for (int m = 0; m < 32; m++) {
        float om0 = __shfl_sync(0xffffffffu, o0, m);   // o[2m]
        float om1 = __shfl_sync(0xffffffffu, o1, m);   // o[2m+1]
        float2 w0 = *(const float2*)&Wc[2 * m][2 * lane];
        float2 w1 = *(const float2*)&Wc[2 * m + 1][2 * lane];
        gg0 = fmaf(om0, w0.x, gg0);
        gg1 = fmaf(om0, w0.y, gg1);
        gg0 = fmaf(om1, w1.x, gg0);
        gg1 = fmaf(om1, w1.y, gg1);
    }
    float2 r;
    r.x = fmaxf(one_minus_beta * o0 + beta * gg0, 0.f);
    r.y = fmaxf(one_minus_beta * o1 + beta * gg1, 0.f);
    *(float2*)&hout[node * HDIM + 2 * lane] = r;
}

// ---------------- final: z[n,k] = sum_p P[p,n]*A[p,k] (symmetric-pair GEMM) ----------------
// FM=64 nodes, 128 threads (4 warps). Thread tile: 4 nodes x 5 k.
#define FM 64
#define FTHR 128
#define KC 32
#define OFF_P   0                          // [KC][64]   (2048)
#define OFF_A   (OFF_P + KC * FM)          // [KC][APR]  (3072)
#define OFF_H   (OFF_A + KC * APR)         // [64][65]   (4160)
#define OFF_N2  (OFF_H + FM * 65)          // [64]
#define FK_SMEM_FLOATS (OFF_N2 + FM)
#define FK_SMEM_BYTES  (FK_SMEM_FLOATS * 4)
// zs overlaid on Pt/At after the main loop (needs 64*40=2560 <= 5120)

__global__ void final_kernel(const float* __restrict__ hin, const float* __restrict__ b1,
                             float* __restrict__ out) {
    extern __shared__ float smem[];
    float* Pt  = smem + OFF_P;
    float* At  = smem + OFF_A;
    float* hs  = smem + OFF_H;
    float* n2s = smem + OFF_N2;
    float* zs  = smem + OFF_P;             // overlay, used after main loop

    int tid = threadIdx.x;
    int n0 = blockIdx.x * FM;

    // load h tile [64][64] -> hs stride 65
#pragma unroll
    for (int q = 0; q < 8; q++) {
        int idx = tid + FTHR * q;          // 0..1023 float4 slots
        int nd = idx >> 4;
        int j4 = idx & 15;
        int gn = n0 + nd;
        float4 v = make_float4(0.f, 0.f, 0.f, 0.f);
        if (gn < N_NODES) v = *(const float4*)&hin[gn * HDIM + j4 * 4];
        float* hr = hs + nd * 65 + j4 * 4;
        hr[0] = v.x; hr[1] = v.y; hr[2] = v.z; hr[3] = v.w;
    }
    __syncthreads();

    if (tid < FM) {
        float s = 0.f;
        const float* hr = hs + tid * 65;
#pragma unroll
        for (int j = 0; j < 64; j++) s = fmaf(hr[j], hr[j], s);
        n2s[tid] = s;
    }

    int g = tid >> 3;         // node group 0..15: nodes 4g..4g+3
    int kg = tid & 7;         // k group 0..7: ks kg*5..kg*5+4
    int kbase = kg * 5;

    ull_t acc0[5], acc1[5];
#pragma unroll
    for (int c = 0; c < 5; c++) { acc0[c] = 0ull; acc1[c] = 0ull; }

    for (int pc = 0; pc < NPAIR; pc += KC) {
        __syncthreads();
        // stage A chunk: KC*APR floats = 768 float4, contiguous
        {
            const float4* src = (const float4*)&g_Apack[pc * APR];
#pragma unroll
            for (int q = 0; q < KC * APR / 4 / FTHR; q++) {   // 6
                int v = tid + FTHR * q;
                *(float4*)&At[v * 4] = src[v];
            }
        }
        // build P chunk: P[pl][nd] = h[nd][i]*h[nd][j]
#pragma unroll
        for (int q = 0; q < KC * FM / FTHR; q++) {            // 16
            int t = tid + FTHR * q;
            int pl = t >> 6;
            int nd = t & 63;
            int p = pc + pl;
            int i = __ldg(&g_pi[p]);
            int j = __ldg(&g_pj[p]);
            Pt[pl * FM + nd] = hs[nd * 65 + i] * hs[nd * 65 + j];
        }
        __syncthreads();

#pragma unroll 4
        for (int kk = 0; kk < KC; kk++) {
            double2 pd = *(const double2*)&Pt[kk * FM + g * 4];
            ull_t p01 = __double_as_longlong(pd.x);
            ull_t p23 = __double_as_longlong(pd.y);
            const float* arow = At + kk * APR + kg * 12;
            double2 a01 = *(const double2*)arow;
            double2 a23 = *(const double2*)(arow + 4);
            ull_t a4 = *(const ull_t*)(arow + 8);
            ull_t a0 = __double_as_longlong(a01.x);
            ull_t a1 = __double_as_longlong(a01.y);
            ull_t a2 = __double_as_longlong(a23.x);
            ull_t a3 = __double_as_longlong(a23.y);
            FMA_F32X2(acc0[0], p01, a0, acc0[0]);
            FMA_F32X2(acc1[0], p23, a0, acc1[0]);
            FMA_F32X2(acc0[1], p01, a1, acc0[1]);
            FMA_F32X2(acc1[1], p23, a1, acc1[1]);
            FMA_F32X2(acc0[2], p01, a2, acc0[2]);
            FMA_F32X2(acc1[2], p23, a2, acc1[2]);
            FMA_F32X2(acc0[3], p01, a3, acc0[3]);
            FMA_F32X2(acc1[3], p23, a3, acc1[3]);
            FMA_F32X2(acc0[4], p01, a4, acc0[4]);
            FMA_F32X2(acc1[4], p23, a4, acc1[4]);
        }
    }
    __syncthreads();   // done with Pt/At; zs overlay becomes safe

    // unpack accumulators -> zs[node][k]
#pragma unroll
    for (int c = 0; c < 5; c++) {
        int k = kbase + c;
        zs[(g * 4 + 0) * C_OUT + k] = __uint_as_float((unsigned)(acc0[c] & 0xffffffffull));
        zs[(g * 4 + 1) * C_OUT + k] = __uint_as_float((unsigned)(acc0[c] >> 32));
        zs[(g * 4 + 2) * C_OUT + k] = __uint_as_float((unsigned)(acc1[c] & 0xffffffffull));
        zs[(g * 4 + 3) * C_OUT + k] = __uint_as_float((unsigned)(acc1[c] >> 32));
    }
    __syncthreads();

    // per-node hyperbolic epilogue + log_softmax
    if (tid < FM) {
        int gn = n0 + tid;
        if (gn < N_NODES) {
            const float MAXN = 1.0f - 4e-3f;
            float n2 = fmaxf(n2s[tid], 1e-15f);   // ||o|| = ||h||^2
            float pn = fminf(n2, MAXN);
            float t = atanhf(pn);
            float scale = t / n2;

            float u[C_OUT];
            float un2 = 0.f;
#pragma unroll
            for (int k = 0; k < C_OUT; k++) {
                float v = scale * zs[tid * C_OUT + k] + b1[k];
                u[k] = v;
                un2 = fmaf(v, v, un2);
            }
            float un = fmaxf(sqrtf(un2), 1e-15f);
            float th = tanhf(un);
            float gsc = fminf(th, MAXN) / un;

            float m = -INFINITY;
#pragma unroll
            for (int k = 0; k < C_OUT; k++) {
                u[k] *= gsc;
                m = fmaxf(m, u[k]);
            }
            float se = 0.f;
#pragma unroll
            for (int k = 0; k < C_OUT; k++) se += expf(u[k] - m);
            float lse = m + logf(se);
#pragma unroll
            for (int k = 0; k < C_OUT; k++) out[gn * C_OUT + k] = u[k] - lse;
        }
    }
}

// ---------------- launch ----------------
// lin0 stays in the 4th launch slot (the ncu-profiled one) to verify the
// prefetch fix: predicted dur <= 40us, issue% >= 40.
extern "C" void kernel_launch(void* const* d_in, const int* in_sizes, int n_in,
                              void* d_out, int out_size) {
    const float* x      = (const float*)d_in[0];
    const int*   row    = (const int*)d_in[1];
    const int*   col    = (const int*)d_in[2];
    const float* ew     = (const float*)d_in[3];
    const float* lin0_w = (const float*)d_in[4];
    const float* lin0_b = (const float*)d_in[5];
    const float* conv_w = (const float*)d_in[6];
    const float* lin1_w = (const float*)d_in[7];
    const float* lin1_b = (const float*)d_in[8];
    float* out = (float*)d_out;

    float* hA = nullptr;
    float* hB = nullptr;
    cudaGetSymbolAddress((void**)&hA, g_hA);
    cudaGetSymbolAddress((void**)&hB, g_hB);

    init_kernel<<<(N_NODES + 255) / 256, 256>>>();                          // 1
    hist_kernel<<<(E_EDGES + 255) / 256, 256>>>(row);                       // 2
    scan_kernel<<<1, 1024>>>();                                             // 3
    lin0_kernel<<<(N_NODES + L0_RT - 1) / L0_RT, 256>>>(x, lin0_w, lin0_b); // 4 <- profiled
    scatter_kernel<<<(E_EDGES + 255) / 256, 256>>>(row, col, ew);           // 5
    apack_kernel<<<(NPAIR * C_OUT + 255) / 256, 256>>>(lin1_w);             // 6

    const float* hin = hA;
    float* hout = hB;
    for (int l = 0; l < L_LAYERS; l++) {
        float beta = logf(0.5f / (float)(l + 1) + 1.0f);
        layer_kernel<<<(N_NODES + 7) / 8, 256>>>(hin, hout, conv_w + l * HDIM * HDIM,
                                                 1.0f - beta, beta);
        const float* tmp = hin;
        hin = hout;
        hout = (float*)tmp;
    }

    cudaFuncSetAttribute(final_kernel, cudaFuncAttributeMaxDynamicSharedMemorySize,
                         FK_SMEM_BYTES);
    final_kernel<<<(N_NODES + FM - 1) / FM, FTHR, FK_SMEM_BYTES>>>(hin, lin1_b, out);
}

// round 8
// speedup vs baseline: 1.1227x; 1.0162x over previous
#include <cuda_runtime.h>
#include <math.h>

#define N_NODES 20000
#define F_IN    512
#define HDIM    64
#define L_LAYERS 8
#define E_EDGES 640000
#define C_OUT   40
#define NPAIR   2080          // 64*65/2 pairs (i<=j)
#define APR     96            // padded A row: 8 kg * 12 floats (10 used, 16B-aligned)

typedef unsigned long long ull_t;

// ---------------- device scratch (no runtime allocation allowed) ----------------
__device__ float g_h0[N_NODES * HDIM];
__device__ float g_hA[N_NODES * HDIM];
__device__ float g_hB[N_NODES * HDIM];
__device__ int   g_cnt[N_NODES];
__device__ int   g_ptr[N_NODES + 1];
__device__ int   g_cursor[N_NODES];
__device__ int2  g_edges[E_EDGES];            // x = col index, y = float bits of weight
__device__ int   g_pi[NPAIR];
__device__ int   g_pj[NPAIR];
__device__ float g_Apack[NPAIR * APR];        // [p][kg][12]: 5 duplicated k-pairs + pad

#define FMA_F32X2(d, a, b, c) \
    asm("fma.rn.f32x2 %0, %1, %2, %3;" : "=l"(d) : "l"(a), "l"(b), "l"(c))

__device__ __forceinline__ ull_t pack2(float lo, float hi) {
    ull_t r;
    asm("mov.b64 %0, {%1, %2};" : "=l"(r) : "f"(lo), "f"(hi));
    return r;
}

// ---------------- init: zero counters + pair index tables ----------------
__global__ void init_kernel() {
    int t = blockIdx.x * blockDim.x + threadIdx.x;
    if (t < N_NODES) g_cnt[t] = 0;
    if (t < NPAIR) {
        int i = 0, off = 0;
        while (off + (HDIM - i) <= t) { off += HDIM - i; i++; }
        g_pi[t] = i;
        g_pj[t] = i + (t - off);
    }
}

__global__ void hist_kernel(const int* __restrict__ row) {
    int e = blockIdx.x * blockDim.x + threadIdx.x;
    if (e < E_EDGES) atomicAdd(&g_cnt[row[e]], 1);
}

// single-block exclusive scan over 20000 counters -> g_ptr, g_cursor
__global__ void scan_kernel() {
    const int T = 1024;
    const int PER = (N_NODES + T - 1) / T;  // 20
    __shared__ int sums[T];
    int t = threadIdx.x;
    int base = t * PER;
    int local[PER];
    int s = 0;
#pragma unroll
    for (int i = 0; i < PER; i++) {
        int idx = base + i;
        int v = (idx < N_NODES) ? g_cnt[idx] : 0;
        local[i] = s;
        s += v;
    }
    sums[t] = s;
    __syncthreads();
    for (int off = 1; off < T; off <<= 1) {
        int v = (t >= off) ? sums[t - off] : 0;
        __syncthreads();
        sums[t] += v;
        __syncthreads();
    }
    int offset = (t == 0) ? 0 : sums[t - 1];
#pragma unroll
    for (int i = 0; i < PER; i++) {
        int idx = base + i;
        if (idx < N_NODES) {
            int p = offset + local[i];
            g_ptr[idx] = p;
            g_cursor[idx] = p;
        }
    }
    if (t == T - 1) g_ptr[N_NODES] = sums[T - 1];
}

__global__ void scatter_kernel(const int* __restrict__ row, const int* __restrict__ col,
                               const float* __restrict__ ew) {
    int e = blockIdx.x * blockDim.x + threadIdx.x;
    if (e < E_EDGES) {
        int r = row[e];
        int pos = atomicAdd(&g_cursor[r], 1);
        g_edges[pos] = make_int2(col[e], __float_as_int(ew[e]));
    }
}

// A[p][k] = W[(i,j),k] + (i!=j ? W[(j,i),k] : 0), duplicated pairs, padded layout
__global__ void apack_kernel(const float* __restrict__ lin1_w) {
    int idx = blockIdx.x * blockDim.x + threadIdx.x;   // 0 .. NPAIR*C_OUT-1
    if (idx < NPAIR * C_OUT) {
        int p = idx / C_OUT;
        int k = idx % C_OUT;
        int i = g_pi[p], j = g_pj[p];
        float v = lin1_w[(i * HDIM + j) * C_OUT + k];
        if (i != j) v += lin1_w[(j * HDIM + i) * C_OUT + k];
        int kg = k / 5, kc = k % 5;
        float* dst = &g_Apack[p * APR + kg * 12 + kc * 2];
        dst[0] = v;
        dst[1] = v;
    }
}

// ---------------- lin0 GEMM: h0 = relu(x @ W + b) ; also seed h ----------------
// K-split x2: 512 threads, halves kh=0/1 each reduce 256 of K=512 into private
// smem buffers; partials combined through smem. Grid 139 = one wave. Prefetch
// double-buffering per half.
#define L0_RT 144
#define L0_XS 149   // padded row stride for Xs (conflict-free STS)
#define L0_XSZ (32 * L0_XS)          // floats per half Xs
#define L0_WSZ (32 * 64)             // floats per half Ws
#define L0_SMEM_FLOATS (2 * L0_XSZ + 2 * L0_WSZ)
#define L0_SMEM_BYTES  (L0_SMEM_FLOATS * 4)
__global__ void lin0_kernel(const float* __restrict__ x, const float* __restrict__ w,
                            const float* __restrict__ b) {
    extern __shared__ float sm[];
    int tid = threadIdx.x;
    int kh = tid >> 8;        // K half: 0 or 1
    int t  = tid & 255;
    int tx = t & 15;
    int ty = t >> 4;
    float* Xs = sm + kh * L0_XSZ;                 // [32][L0_XS]
    float* Ws = sm + 2 * L0_XSZ + kh * L0_WSZ;    // [32][64]
    int row0 = blockIdx.x * L0_RT;
    int kbase = kh * 256;

    ull_t acc0[9], acc1[9];
#pragma unroll
    for (int m = 0; m < 9; m++) { acc0[m] = 0ull; acc1[m] = 0ull; }

    // per-thread load coordinates (within a half: 256 threads)
    float4 xv[5];
    float4 wv[2];
    int xr[5], xk4[5];
    bool xok[5];
#pragma unroll
    for (int q = 0; q < 5; q++) {
        int idx = t + 256 * q;
        xok[q] = (idx < L0_RT * 8);
        xr[q] = idx >> 3;
        xk4[q] = idx & 7;
    }
    int wkk[2], wc4[2];
#pragma unroll
    for (int q = 0; q < 2; q++) {
        int idx = t + 256 * q;
        wkk[q] = idx >> 4;
        wc4[q] = idx & 15;
    }

    // prefetch chunk 0 of this half
#pragma unroll
    for (int q = 0; q < 5; q++) {
        xv[q] = make_float4(0.f, 0.f, 0.f, 0.f);
        if (xok[q]) {
            int gr = row0 + xr[q];
            if (gr < N_NODES) xv[q] = *(const float4*)&x[gr * F_IN + kbase + xk4[q] * 4];
        }
    }
#pragma unroll
    for (int q = 0; q < 2; q++)
        wv[q] = *(const float4*)&w[(kbase + wkk[q]) * HDIM + wc4[q] * 4];

    for (int c = 0; c < 8; c++) {
        __syncthreads();
#pragma unroll
        for (int q = 0; q < 5; q++) {
            if (xok[q]) {
                int r = xr[q], k4 = xk4[q];
                Xs[(k4 * 4 + 0) * L0_XS + r] = xv[q].x;
                Xs[(k4 * 4 + 1) * L0_XS + r] = xv[q].y;
                Xs[(k4 * 4 + 2) * L0_XS + r] = xv[q].z;
                Xs[(k4 * 4 + 3) * L0_XS + r] = xv[q].w;
            }
        }
#pragma unroll
        for (int q = 0; q < 2; q++)
            *(float4*)&Ws[wkk[q] * 64 + wc4[q] * 4] = wv[q];
        __syncthreads();

        if (c + 1 < 8) {
            int k0 = kbase + (c + 1) * 32;
#pragma unroll
            for (int q = 0; q < 5; q++) {
                if (xok[q]) {
                    int gr = row0 + xr[q];
                    if (gr < N_NODES)
                        xv[q] = *(const float4*)&x[gr * F_IN + k0 + xk4[q] * 4];
                }
            }
#pragma unroll
            for (int q = 0; q < 2; q++)
                wv[q] = *(const float4*)&w[(k0 + wkk[q]) * HDIM + wc4[q] * 4];
        }

#pragma unroll
        for (int kk = 0; kk < 32; kk++) {
            double2 bd = *(const double2*)&Ws[kk * 64 + tx * 4];
            ull_t b01 = __double_as_longlong(bd.x);
            ull_t b23 = __double_as_longlong(bd.y);
#pragma unroll
            for (int m = 0; m < 9; m++) {
                float a = Xs[kk * L0_XS + ty * 9 + m];
                ull_t pa = pack2(a, a);
                FMA_F32X2(acc0[m], pa, b01, acc0[m]);
                FMA_F32X2(acc1[m], pa, b23, acc1[m]);
            }
        }
    }

    // combine halves through smem (reuse buffer: 256*36 = 9216 <= L0_SMEM_FLOATS)
    __syncthreads();
    float* part = sm;
    if (kh == 1) {
#pragma unroll
        for (int m = 0; m < 9; m++) {
            float4 v;
            v.x = __uint_as_float((unsigned)(acc0[m] & 0xffffffffull));
            v.y = __uint_as_float((unsigned)(acc0[m] >> 32));
            v.z = __uint_as_float((unsigned)(acc1[m] & 0xffffffffull));
            v.w = __uint_as_float((unsigned)(acc1[m] >> 32));
            *(float4*)&part[t * 36 + m * 4] = v;
        }
    }
    __syncthreads();
    if (kh == 0) {
        float4 bv = *(const float4*)&b[tx * 4];
#pragma unroll
        for (int m = 0; m < 9; m++) {
            int gr = row0 + ty * 9 + m;
            if (gr < N_NODES) {
                float4 p = *(const float4*)&part[t * 36 + m * 4];
                float4 r;
                r.x = fmaxf(__uint_as_float((unsigned)(acc0[m] & 0xffffffffull)) + p.x + bv.x, 0.f);
                r.y = fmaxf(__uint_as_float((unsigned)(acc0[m] >> 32)) + p.y + bv.y, 0.f);
                r.z = fmaxf(__uint_as_float((unsigned)(acc1[m] & 0xffffffffull)) + p.z + bv.z, 0.f);
                r.w = fmaxf(__uint_as_float((unsigned)(acc1[m] >> 32)) + p.w + bv.w, 0.f);
                *(float4*)&g_h0[gr * HDIM + tx * 4] = r;
                *(float4*)&g_hA[gr * HDIM + tx * 4] = r;
            }
        }
    }
}

// ---------------- fused GCN2 layer: float2 gathers, 8-edge MLP ----------------
// one warp per node; lane owns columns 2*lane, 2*lane+1.
__global__ void layer_kernel(const float* __restrict__ hin, float* __restrict__ hout,
                             const float* __restrict__ convw, float one_minus_beta, float beta) {
    __shared__ float Wc[64][64];
    int tid = threadIdx.x;
#pragma unroll
    for (int q = 0; q < 4; q++) {
        int idx = tid + 256 * q;
        *(float4*)&Wc[0][idx * 4] = *(const float4*)&convw[idx * 4];
    }
    __syncthreads();

    int warp = tid >> 5, lane = tid & 31;
    int node = blockIdx.x * 8 + warp;
    if (node >= N_NODES) return;

    int s = g_ptr[node];
    int e = g_ptr[node + 1];
    float acc0 = 0.f, acc1 = 0.f;
    int i = s;
    if ((i & 1) && i < e) {
        int2 a0 = g_edges[i];
        float wv = __int_as_float(a0.y);
        float2 v = __ldg((const float2*)&hin[a0.x * HDIM + 2 * lane]);
        acc0 = fmaf(wv, v.x, acc0);
        acc1 = fmaf(wv, v.y, acc1);
        i++;
    }
    // 8 edges per iteration: 8 independent gathers in flight
    for (; i + 8 <= e; i += 8) {
        int4 e01 = *(const int4*)&g_edges[i];
        int4 e23 = *(const int4*)&g_edges[i + 2];
        int4 e45 = *(const int4*)&g_edges[i + 4];
        int4 e67 = *(const int4*)&g_edges[i + 6];
        float2 v0 = __ldg((const float2*)&hin[e01.x * HDIM + 2 * lane]);
        float2 v1 = __ldg((const float2*)&hin[e01.z * HDIM + 2 * lane]);
        float2 v2 = __ldg((const float2*)&hin[e23.x * HDIM + 2 * lane]);
        float2 v3 = __ldg((const float2*)&hin[e23.z * HDIM + 2 * lane]);
        float2 v4 = __ldg((const float2*)&hin[e45.x * HDIM + 2 * lane]);
        float2 v5 = __ldg((const float2*)&hin[e45.z * HDIM + 2 * lane]);
        float2 v6 = __ldg((const float2*)&hin[e67.x * HDIM + 2 * lane]);
        float2 v7 = __ldg((const float2*)&hin[e67.z * HDIM + 2 * lane]);
        acc0 = fmaf(__int_as_float(e01.y), v0.x, acc0);
        acc1 = fmaf(__int_as_float(e01.y), v0.y, acc1);
        acc0 = fmaf(__int_as_float(e01.w), v1.x, acc0);
        acc1 = fmaf(__int_as_float(e01.w), v1.y, acc1);
        acc0 = fmaf(__int_as_float(e23.y), v2.x, acc0);
        acc1 = fmaf(__int_as_float(e23.y), v2.y, acc1);
        acc0 = fmaf(__int_as_float(e23.w), v3.x, acc0);
        acc1 = fmaf(__int_as_float(e23.w), v3.y, acc1);
        acc0 = fmaf(__int_as_float(e45.y), v4.x, acc0);
        acc1 = fmaf(__int_as_float(e45.y), v4.y, acc1);
        acc0 = fmaf(__int_as_float(e45.w), v5.x, acc0);
        acc1 = fmaf(__int_as_float(e45.w), v5.y, acc1);
        acc0 = fmaf(__int_as_float(e67.y), v6.x, acc0);
        acc1 = fmaf(__int_as_float(e67.y), v6.y, acc1);
        acc0 = fmaf(__int_as_float(e67.w), v7.x, acc0);
        acc1 = fmaf(__int_as_float(e67.w), v7.y, acc1);
    }
    for (; i + 4 <= e; i += 4) {
        int4 e01 = *(const int4*)&g_edges[i];
        int4 e23 = *(const int4*)&g_edges[i + 2];
        float2 v0 = __ldg((const float2*)&hin[e01.x * HDIM + 2 * lane]);
        float2 v1 = __ldg((const float2*)&hin[e01.z * HDIM + 2 * lane]);
        float2 v2 = __ldg((const float2*)&hin[e23.x * HDIM + 2 * lane]);
        float2 v3 = __ldg((const float2*)&hin[e23.z * HDIM + 2 * lane]);
        acc0 = fmaf(__int_as_float(e01.y), v0.x, acc0);
        acc1 = fmaf(__int_as_float(e01.y), v0.y, acc1);
        acc0 = fmaf(__int_as_float(e01.w), v1.x, acc0);
        acc1 = fmaf(__int_as_float(e01.w), v1.y, acc1);
        acc0 = fmaf(__int_as_float(e23.y), v2.x, acc0);
        acc1 = fmaf(__int_as_float(e23.y), v2.y, acc1);
        acc0 = fmaf(__int_as_float(e23.w), v3.x, acc0);
        acc1 = fmaf(__int_as_float(e23.w), v3.y, acc1);
    }
    for (; i < e; i++) {
        int2 a0 = g_edges[i];
        float wv = __int_as_float(a0.y);
        float2 v = __ldg((const float2*)&hin[a0.x * HDIM + 2 * lane]);
        acc0 = fmaf(wv, v.x, acc0);
        acc1 = fmaf(wv, v.y, acc1);
    }

    float2 h0v = *(const float2*)&g_h0[node * HDIM + 2 * lane];
    float o0 = 0.9f * acc0 + 0.1f * h0v.x;   // col 2*lane
    float o1 = 0.9f * acc1 + 0.1f * h0v.y;   // col 2*lane+1

    // conv: gg[c] = sum_k o[k] * Wc[k][c]
    float gg0 = 0.f, gg1 = 0.f;
#pragma unroll
    for (int m = 0; m < 32; m++) {
        float om0 = __shfl_sync(0xffffffffu, o0, m);   // o[2m]
        float om1 = __shfl_sync(0xffffffffu, o1, m);   // o[2m+1]
        float2 w0 = *(const float2*)&Wc[2 * m][2 * lane];
        float2 w1 = *(const float2*)&Wc[2 * m + 1][2 * lane];
        gg0 = fmaf(om0, w0.x, gg0);
        gg1 = fmaf(om0, w0.y, gg1);
        gg0 = fmaf(om1, w1.x, gg0);
        gg1 = fmaf(om1, w1.y, gg1);
    }
    float2 r;
    r.x = fmaxf(one_minus_beta * o0 + beta * gg0, 0.f);
    r.y = fmaxf(one_minus_beta * o1 + beta * gg1, 0.f);
    *(float2*)&hout[node * HDIM + 2 * lane] = r;
}

// ---------------- final: z[n,k] = sum_p P[p,n]*A[p,k] (symmetric-pair GEMM) ----------------
// FM=64 nodes, 128 threads (4 warps). Thread tile: 4 nodes x 5 k.
#define FM 64
#define FTHR 128
#define KC 32
#define OFF_P   0                          // [KC][64]   (2048)
#define OFF_A   (OFF_P + KC * FM)          // [KC][APR]  (3072)
#define OFF_H   (OFF_A + KC * APR)         // [64][65]   (4160)
#define OFF_N2  (OFF_H + FM * 65)          // [64]
#define FK_SMEM_FLOATS (OFF_N2 + FM)
#define FK_SMEM_BYTES  (FK_SMEM_FLOATS * 4)
// zs overlaid on Pt/At after the main loop (needs 64*40=2560 <= 5120)

__global__ void final_kernel(const float* __restrict__ hin, const float* __restrict__ b1,
                             float* __restrict__ out) {
    extern __shared__ float smem[];
    float* Pt  = smem + OFF_P;
    float* At  = smem + OFF_A;
    float* hs  = smem + OFF_H;
    float* n2s = smem + OFF_N2;
    float* zs  = smem + OFF_P;             // overlay, used after main loop

    int tid = threadIdx.x;
    int n0 = blockIdx.x * FM;

    // load h tile [64][64] -> hs stride 65
#pragma unroll
    for (int q = 0; q < 8; q++) {
        int idx = tid + FTHR * q;          // 0..1023 float4 slots
        int nd = idx >> 4;
        int j4 = idx & 15;
        int gn = n0 + nd;
        float4 v = make_float4(0.f, 0.f, 0.f, 0.f);
        if (gn < N_NODES) v = *(const float4*)&hin[gn * HDIM + j4 * 4];
        float* hr = hs + nd * 65 + j4 * 4;
        hr[0] = v.x; hr[1] = v.y; hr[2] = v.z; hr[3] = v.w;
    }
    __syncthreads();

    if (tid < FM) {
        float s = 0.f;
        const float* hr = hs + tid * 65;
#pragma unroll
        for (int j = 0; j < 64; j++) s = fmaf(hr[j], hr[j], s);
        n2s[tid] = s;
    }

    int g = tid >> 3;         // node group 0..15: nodes 4g..4g+3
    int kg = tid & 7;         // k group 0..7: ks kg*5..kg*5+4
    int kbase = kg * 5;

    ull_t acc0[5], acc1[5];
#pragma unroll
    for (int c = 0; c < 5; c++) { acc0[c] = 0ull; acc1[c] = 0ull; }

    for (int pc = 0; pc < NPAIR; pc += KC) {
        __syncthreads();
        // stage A chunk: KC*APR floats = 768 float4, contiguous
        {
            const float4* src = (const float4*)&g_Apack[pc * APR];
#pragma unroll
            for (int q = 0; q < KC * APR / 4 / FTHR; q++) {   // 6
                int v = tid + FTHR * q;
                *(float4*)&At[v * 4] = src[v];
            }
        }
        // build P chunk: P[pl][nd] = h[nd][i]*h[nd][j]
#pragma unroll
        for (int q = 0; q < KC * FM / FTHR; q++) {            // 16
            int t = tid + FTHR * q;
            int pl = t >> 6;
            int nd = t & 63;
            int p = pc + pl;
            int i = __ldg(&g_pi[p]);
            int j = __ldg(&g_pj[p]);
            Pt[pl * FM + nd] = hs[nd * 65 + i] * hs[nd * 65 + j];
        }
        __syncthreads();

#pragma unroll 4
        for (int kk = 0; kk < KC; kk++) {
            double2 pd = *(const double2*)&Pt[kk * FM + g * 4];
            ull_t p01 = __double_as_longlong(pd.x);
            ull_t p23 = __double_as_longlong(pd.y);
            const float* arow = At + kk * APR + kg * 12;
            double2 a01 = *(const double2*)arow;
            double2 a23 = *(const double2*)(arow + 4);
            ull_t a4 = *(const ull_t*)(arow + 8);
            ull_t a0 = __double_as_longlong(a01.x);
            ull_t a1 = __double_as_longlong(a01.y);
            ull_t a2 = __double_as_longlong(a23.x);
            ull_t a3 = __double_as_longlong(a23.y);
            FMA_F32X2(acc0[0], p01, a0, acc0[0]);
            FMA_F32X2(acc1[0], p23, a0, acc1[0]);
            FMA_F32X2(acc0[1], p01, a1, acc0[1]);
            FMA_F32X2(acc1[1], p23, a1, acc1[1]);
            FMA_F32X2(acc0[2], p01, a2, acc0[2]);
            FMA_F32X2(acc1[2], p23, a2, acc1[2]);
            FMA_F32X2(acc0[3], p01, a3, acc0[3]);
            FMA_F32X2(acc1[3], p23, a3, acc1[3]);
            FMA_F32X2(acc0[4], p01, a4, acc0[4]);
            FMA_F32X2(acc1[4], p23, a4, acc1[4]);
        }
    }
    __syncthreads();   // done with Pt/At; zs overlay becomes safe

    // unpack accumulators -> zs[node][k]
#pragma unroll
    for (int c = 0; c < 5; c++) {
        int k = kbase + c;
        zs[(g * 4 + 0) * C_OUT + k] = __uint_as_float((unsigned)(acc0[c] & 0xffffffffull));
        zs[(g * 4 + 1) * C_OUT + k] = __uint_as_float((unsigned)(acc0[c] >> 32));
        zs[(g * 4 + 2) * C_OUT + k] = __uint_as_float((unsigned)(acc1[c] & 0xffffffffull));
        zs[(g * 4 + 3) * C_OUT + k] = __uint_as_float((unsigned)(acc1[c] >> 32));
    }
    __syncthreads();

    // per-node hyperbolic epilogue + log_softmax
    if (tid < FM) {
        int gn = n0 + tid;
        if (gn < N_NODES) {
            const float MAXN = 1.0f - 4e-3f;
            float n2 = fmaxf(n2s[tid], 1e-15f);   // ||o|| = ||h||^2
            float pn = fminf(n2, MAXN);
            float t = atanhf(pn);
            float scale = t / n2;

            float u[C_OUT];
            float un2 = 0.f;
#pragma unroll
            for (int k = 0; k < C_OUT; k++) {
                float v = scale * zs[tid * C_OUT + k] + b1[k];
                u[k] = v;
                un2 = fmaf(v, v, un2);
            }
            float un = fmaxf(sqrtf(un2), 1e-15f);
            float th = tanhf(un);
            float gsc = fminf(th, MAXN) / un;

            float m = -INFINITY;
#pragma unroll
            for (int k = 0; k < C_OUT; k++) {
                u[k] *= gsc;
                m = fmaxf(m, u[k]);
            }
            float se = 0.f;
#pragma unroll
            for (int k = 0; k < C_OUT; k++) se += expf(u[k] - m);
            float lse = m + logf(se);
#pragma unroll
            for (int k = 0; k < C_OUT; k++) out[gn * C_OUT + k] = u[k] - lse;
        }
    }
}

// ---------------- launch ----------------
// lin0 stays in the 4th launch slot (the ncu-profiled one) to verify the
// K-split fix: predicted dur <= 30us, occ 25%, issue >= 60%.
extern "C" void kernel_launch(void* const* d_in, const int* in_sizes, int n_in,
                              void* d_out, int out_size) {
    const float* x      = (const float*)d_in[0];
    const int*   row    = (const int*)d_in[1];
    const int*   col    = (const int*)d_in[2];
    const float* ew     = (const float*)d_in[3];
    const float* lin0_w = (const float*)d_in[4];
    const float* lin0_b = (const float*)d_in[5];
    const float* conv_w = (const float*)d_in[6];
    const float* lin1_w = (const float*)d_in[7];
    const float* lin1_b = (const float*)d_in[8];
    float* out = (float*)d_out;

    float* hA = nullptr;
    float* hB = nullptr;
    cudaGetSymbolAddress((void**)&hA, g_hA);
    cudaGetSymbolAddress((void**)&hB, g_hB);

    init_kernel<<<(N_NODES + 255) / 256, 256>>>();                          // 1
    hist_kernel<<<(E_EDGES + 255) / 256, 256>>>(row);                       // 2
    scan_kernel<<<1, 1024>>>();                                             // 3
    cudaFuncSetAttribute(lin0_kernel, cudaFuncAttributeMaxDynamicSharedMemorySize,
                         L0_SMEM_BYTES);
    lin0_kernel<<<(N_NODES + L0_RT - 1) / L0_RT, 512, L0_SMEM_BYTES>>>(
        x, lin0_w, lin0_b);                                                 // 4 <- profiled
    scatter_kernel<<<(E_EDGES + 255) / 256, 256>>>(row, col, ew);           // 5
    apack_kernel<<<(NPAIR * C_OUT + 255) / 256, 256>>>(lin1_w);             // 6

    const float* hin = hA;
    float* hout = hB;
    for (int l = 0; l < L_LAYERS; l++) {
        float beta = logf(0.5f / (float)(l + 1) + 1.0f);
        layer_kernel<<<(N_NODES + 7) / 8, 256>>>(hin, hout, conv_w + l * HDIM * HDIM,
                                                 1.0f - beta, beta);
        const float* tmp = hin;
        hin = hout;
        hout = (float*)tmp;
    }

    cudaFuncSetAttribute(final_kernel, cudaFuncAttributeMaxDynamicSharedMemorySize,
                         FK_SMEM_BYTES);
    final_kernel<<<(N_NODES + FM - 1) / FM, FTHR, FK_SMEM_BYTES>>>(hin, lin1_b, out);
}